// round 1
// baseline (speedup 1.0000x reference)
#include <cuda_runtime.h>
#include <math.h>

#define BB 64
#define SS 512
#define HH 768
#define LL 9
#define NTOK (BB*SS)
#define TPW 8            // tokens per warp in the main kernel
#define WPAD 12          // padded W row stride (floats): conflict-free + float4-able

// destination slot for each original token (or -1 if masked out)
__device__ int g_pos[NTOK];

// ---------------------------------------------------------------------------
// Kernel 1: per-batch-row stable stream-compaction scan.
// One block per row (64 blocks x 512 threads). g_pos[b*S+s] = exclusive
// prefix of valid_mask if valid, else -1.
// ---------------------------------------------------------------------------
__global__ void scan_kernel(const int* __restrict__ mask) {
    __shared__ int wtot[16];
    int b = blockIdx.x;
    int s = threadIdx.x;
    int m = mask[b * SS + s];
    int v = m;
    #pragma unroll
    for (int o = 1; o < 32; o <<= 1) {
        int n = __shfl_up_sync(0xffffffffu, v, o);
        if ((s & 31) >= o) v += n;
    }
    if ((s & 31) == 31) wtot[s >> 5] = v;
    __syncthreads();
    if (s < 16) {
        int t = wtot[s];
        #pragma unroll
        for (int o = 1; o < 16; o <<= 1) {
            int n = __shfl_up_sync(0x0000ffffu, t, o);
            if (s >= o) t += n;
        }
        wtot[s] = t;
    }
    __syncthreads();
    int incl = v + ((s >> 5) ? wtot[(s >> 5) - 1] : 0);
    g_pos[b * SS + s] = m ? (incl - 1) : -1;
}

// ---------------------------------------------------------------------------
// Kernel 2: fill entire output with softmax(bias). Valid slots get
// overwritten by the main kernel; tail slots correspond to the zero rows of
// the compacted tensor, whose logits are exactly softmax(0 @ W + b).
// Also covers the 0xAA-poisoned buffer.
// ---------------------------------------------------------------------------
__global__ void fill_kernel(const float* __restrict__ bias, float* __restrict__ out) {
    float e[LL];
    float mx = bias[0];
    #pragma unroll
    for (int j = 1; j < LL; j++) mx = fmaxf(mx, bias[j]);
    float ssum = 0.f;
    #pragma unroll
    for (int j = 0; j < LL; j++) { e[j] = expf(bias[j] - mx); ssum += e[j]; }
    float inv = 1.f / ssum;
    int tok = blockIdx.x * blockDim.x + threadIdx.x;
    if (tok < NTOK) {
        float* o = out + (size_t)tok * LL;
        #pragma unroll
        for (int j = 0; j < LL; j++) o[j] = e[j] * inv;
    }
}

// ---------------------------------------------------------------------------
// Kernel 3: fused tall-skinny GEMM [NTOK,768]@[768,9] + bias + softmax +
// compacting scatter. Warp handles TPW=8 tokens; lane l owns k in {l+32i},
// W cached in smem padded to stride 12 (bank-conflict-free float4 reads),
// X streamed from HBM fully coalesced (LDG.32, 128B/warp/instr).
// ---------------------------------------------------------------------------
__global__ __launch_bounds__(128) void main_kernel(
    const float* __restrict__ X, const float* __restrict__ W,
    const float* __restrict__ bias, float* __restrict__ out) {

    __shared__ float shW[HH * WPAD];
    int tid = threadIdx.x;

    // cooperative W load into padded smem
    for (int idx = tid; idx < HH * LL; idx += blockDim.x) {
        int k = idx / LL;
        int j = idx - k * LL;
        shW[k * WPAD + j] = W[idx];
    }
    __syncthreads();

    int lane = tid & 31;
    int warp = (blockIdx.x * blockDim.x + tid) >> 5;
    int tok0 = warp * TPW;
    const float* xb = X + (size_t)tok0 * HH;

    float acc[TPW][LL];
    #pragma unroll
    for (int t = 0; t < TPW; t++)
        #pragma unroll
        for (int j = 0; j < LL; j++) acc[t][j] = 0.f;

    const float4* shW4 = (const float4*)shW;

    #pragma unroll 4
    for (int i = 0; i < HH / 32; i++) {       // 24 iterations
        int k = i * 32 + lane;
        float4 w0 = shW4[k * 3 + 0];          // W[k][0..3]
        float4 w1 = shW4[k * 3 + 1];          // W[k][4..7]
        float4 w2 = shW4[k * 3 + 2];          // W[k][8], pad, pad, pad
        #pragma unroll
        for (int t = 0; t < TPW; t++) {
            float xv = xb[t * HH + k];
            acc[t][0] = fmaf(xv, w0.x, acc[t][0]);
            acc[t][1] = fmaf(xv, w0.y, acc[t][1]);
            acc[t][2] = fmaf(xv, w0.z, acc[t][2]);
            acc[t][3] = fmaf(xv, w0.w, acc[t][3]);
            acc[t][4] = fmaf(xv, w1.x, acc[t][4]);
            acc[t][5] = fmaf(xv, w1.y, acc[t][5]);
            acc[t][6] = fmaf(xv, w1.z, acc[t][6]);
            acc[t][7] = fmaf(xv, w1.w, acc[t][7]);
            acc[t][8] = fmaf(xv, w2.x, acc[t][8]);
        }
    }

    // full-warp butterfly reduction: every lane ends with complete sums
    #pragma unroll
    for (int t = 0; t < TPW; t++)
        #pragma unroll
        for (int j = 0; j < LL; j++)
            #pragma unroll
            for (int o = 16; o > 0; o >>= 1)
                acc[t][j] += __shfl_xor_sync(0xffffffffu, acc[t][j], o);

    // lanes 0..TPW-1 each finalize one token (static acc indexing via unroll)
    #pragma unroll
    for (int t = 0; t < TPW; t++) {
        if (lane == t) {
            int tok = tok0 + t;
            int pos = g_pos[tok];
            if (pos >= 0) {
                float v[LL];
                float mx = -1e30f;
                #pragma unroll
                for (int j = 0; j < LL; j++) {
                    v[j] = acc[t][j] + bias[j];
                    mx = fmaxf(mx, v[j]);
                }
                float ssum = 0.f;
                #pragma unroll
                for (int j = 0; j < LL; j++) { v[j] = expf(v[j] - mx); ssum += v[j]; }
                float inv = 1.f / ssum;
                int row = tok >> 9;              // / SS
                float* o = out + ((size_t)row * SS + pos) * LL;
                #pragma unroll
                for (int j = 0; j < LL; j++) o[j] = v[j] * inv;
            }
        }
    }
}

// ---------------------------------------------------------------------------
// Launch. Inputs (metadata order): sequence_output f32[64*512*768],
// valid_mask i32[64*512], W f32[768*9], b f32[9]. Output f32[64*512*9].
// ---------------------------------------------------------------------------
extern "C" void kernel_launch(void* const* d_in, const int* in_sizes, int n_in,
                              void* d_out, int out_size) {
    const float* X    = (const float*)d_in[0];
    const int*   mask = (const int*)d_in[1];
    const float* W    = (const float*)d_in[2];
    const float* bias = (const float*)d_in[3];
    float* out = (float*)d_out;

    scan_kernel<<<BB, SS>>>(mask);
    fill_kernel<<<(NTOK + 255) / 256, 256>>>(bias, out);
    main_kernel<<<NTOK / (TPW * 4), 128>>>(X, W, bias, out);
}

// round 2
// speedup vs baseline: 1.3478x; 1.3478x over previous
#include <cuda_runtime.h>
#include <math.h>

#define BB 64
#define SS 512
#define HH 768
#define LL 9
#define NTOK (BB*SS)
#define TPW 8              // tokens per warp
#define WPB 4              // warps per block
#define TOKPB (TPW*WPB)    // 32 tokens per block (all within one row: 512/32=16 blocks/row)
#define WPAD 12            // padded W row stride in floats: conflict-free LDS.128

typedef unsigned long long u64;

__device__ __forceinline__ u64 pack2(float lo, float hi) {
    u64 r; asm("mov.b64 %0, {%1, %2};" : "=l"(r) : "f"(lo), "f"(hi)); return r;
}
__device__ __forceinline__ void unpack2(u64 v, float &lo, float &hi) {
    asm("mov.b64 {%0, %1}, %2;" : "=f"(lo), "=f"(hi) : "l"(v));
}
__device__ __forceinline__ void ffma2(u64 &d, u64 a, u64 b) {
    asm("fma.rn.f32x2 %0, %1, %2, %0;" : "+l"(d) : "l"(a), "l"(b));
}
__device__ __forceinline__ u64 fadd2(u64 a, u64 b) {
    u64 r; asm("add.rn.f32x2 %0, %1, %2;" : "=l"(r) : "l"(a), "l"(b)); return r;
}

// ---------------------------------------------------------------------------
// Single fused kernel:
//   1. per-block re-scan of this row's valid_mask -> slot code per token
//      (valid -> compacted slot, invalid -> tail slot; bijection over [0,512))
//   2. tall-skinny GEMM [8 tok/warp, 768] @ [768, 9] with packed f32x2 FMAs
//   3. bias + softmax + scatter (invalid tokens write softmax(bias))
// ---------------------------------------------------------------------------
__global__ __launch_bounds__(128) void bertner_kernel(
    const float* __restrict__ X, const int* __restrict__ mask,
    const float* __restrict__ W, const float* __restrict__ bias,
    float* __restrict__ out) {

    __shared__ float shW[HH * WPAD];
    __shared__ int   sh_slot[TOKPB];
    __shared__ int   sh_wsum[WPB];

    int tid  = threadIdx.x;
    int lane = tid & 31;
    int wid  = tid >> 5;

    // ---- cooperative W load into padded smem ----
    for (int idx = tid; idx < HH * LL; idx += 128) {
        int k = idx / LL;
        int j = idx - k * LL;
        shW[k * WPAD + j] = W[idx];
    }

    // ---- per-row compaction scan (each block redundantly scans its row) ----
    int tokblk = blockIdx.x * TOKPB;
    int row    = tokblk >> 9;          // / SS
    int r0     = tokblk & (SS - 1);    // row-local start of this block's tokens

    int4 m4 = ((const int4*)(mask + row * SS))[tid];   // tokens 4*tid .. 4*tid+3
    int msum = m4.x + m4.y + m4.z + m4.w;
    int v = msum;
    #pragma unroll
    for (int o = 1; o < 32; o <<= 1) {
        int n = __shfl_up_sync(0xffffffffu, v, o);
        if (lane >= o) v += n;
    }
    if (lane == 31) sh_wsum[wid] = v;
    __syncthreads();

    int wpre = 0;
    #pragma unroll
    for (int w = 0; w < WPB; w++) if (w < wid) wpre += sh_wsum[w];
    int total = sh_wsum[0] + sh_wsum[1] + sh_wsum[2] + sh_wsum[3];
    int run = wpre + v - msum;         // exclusive valid-prefix before token 4*tid

    int mm[4] = {m4.x, m4.y, m4.z, m4.w};
    #pragma unroll
    for (int c = 0; c < 4; c++) {
        int sc = 4 * tid + c;
        int code;
        if (mm[c]) { code = run; run++; }
        else       { code = ~(total + sc - run); }   // tail slot, encoded negative
        if (sc >= r0 && sc < r0 + TOKPB) sh_slot[sc - r0] = code;
    }
    __syncthreads();   // covers shW + sh_slot

    // ---- main GEMM: warp handles 8 tokens, lane owns k = lane + 32*i ----
    int tok0 = tokblk + wid * TPW;
    const float* xb = X + (size_t)tok0 * HH;

    u64 acc[TPW/2][LL];
    #pragma unroll
    for (int p = 0; p < TPW/2; p++)
        #pragma unroll
        for (int j = 0; j < LL; j++) acc[p][j] = 0ull;

    const float4* shW4 = (const float4*)shW;

    #pragma unroll 2
    for (int i = 0; i < HH / 32; i++) {       // 24 iterations
        int k = i * 32 + lane;
        float4 w0 = shW4[k * 3 + 0];
        float4 w1 = shW4[k * 3 + 1];
        float4 w2 = shW4[k * 3 + 2];
        float xv[TPW];
        #pragma unroll
        for (int t = 0; t < TPW; t++) xv[t] = xb[t * HH + k];
        u64 xp[TPW/2];
        #pragma unroll
        for (int p = 0; p < TPW/2; p++) xp[p] = pack2(xv[2*p], xv[2*p+1]);

        float wv[LL] = {w0.x, w0.y, w0.z, w0.w, w1.x, w1.y, w1.z, w1.w, w2.x};
        #pragma unroll
        for (int j = 0; j < LL; j++) {
            u64 wp = pack2(wv[j], wv[j]);
            #pragma unroll
            for (int p = 0; p < TPW/2; p++) ffma2(acc[p][j], xp[p], wp);
        }
    }

    // ---- packed butterfly reduction: every lane ends with full sums ----
    #pragma unroll
    for (int p = 0; p < TPW/2; p++)
        #pragma unroll
        for (int j = 0; j < LL; j++)
            #pragma unroll
            for (int o = 16; o > 0; o >>= 1) {
                u64 other = __shfl_xor_sync(0xffffffffu, acc[p][j], o);
                acc[p][j] = fadd2(acc[p][j], other);
            }

    // ---- bias + bias-softmax precompute (cheap, per thread) ----
    float bb[LL], be[LL];
    #pragma unroll
    for (int j = 0; j < LL; j++) bb[j] = bias[j];
    float bmx = bb[0];
    #pragma unroll
    for (int j = 1; j < LL; j++) bmx = fmaxf(bmx, bb[j]);
    float bsum = 0.f;
    #pragma unroll
    for (int j = 0; j < LL; j++) { be[j] = expf(bb[j] - bmx); bsum += be[j]; }
    float binv = 1.f / bsum;

    // ---- finalize: lanes 0..7 each own one token (static acc indexing) ----
    #pragma unroll
    for (int t = 0; t < TPW; t++) {
        if (lane == t) {
            int code = sh_slot[wid * TPW + t];
            if (code >= 0) {
                float v[LL];
                float mx = -1e30f;
                #pragma unroll
                for (int j = 0; j < LL; j++) {
                    float lo, hi;
                    unpack2(acc[t >> 1][j], lo, hi);
                    v[j] = ((t & 1) ? hi : lo) + bb[j];
                    mx = fmaxf(mx, v[j]);
                }
                float ssum = 0.f;
                #pragma unroll
                for (int j = 0; j < LL; j++) { v[j] = expf(v[j] - mx); ssum += v[j]; }
                float inv = 1.f / ssum;
                float* o = out + ((size_t)row * SS + code) * LL;
                #pragma unroll
                for (int j = 0; j < LL; j++) o[j] = v[j] * inv;
            } else {
                int islot = ~code;
                float* o = out + ((size_t)row * SS + islot) * LL;
                #pragma unroll
                for (int j = 0; j < LL; j++) o[j] = be[j] * binv;
            }
        }
    }
}

// ---------------------------------------------------------------------------
// Launch. Inputs (metadata order): sequence_output f32[64*512*768],
// valid_mask i32[64*512], W f32[768*9], b f32[9]. Output f32[64*512*9].
// ---------------------------------------------------------------------------
extern "C" void kernel_launch(void* const* d_in, const int* in_sizes, int n_in,
                              void* d_out, int out_size) {
    const float* X    = (const float*)d_in[0];
    const int*   mask = (const int*)d_in[1];
    const float* W    = (const float*)d_in[2];
    const float* bias = (const float*)d_in[3];
    float* out = (float*)d_out;

    bertner_kernel<<<NTOK / TOKPB, 128>>>(X, mask, W, bias, out);
}